// round 1
// baseline (speedup 1.0000x reference)
#include <cuda_runtime.h>
#include <cuda_bf16.h>
#include <math.h>

// ---------------------------------------------------------------------------
// 25-pt (radius-4, 3-axis) wave stencil, 10 scan steps (first is trivial copy),
// then loss = mean((out-ref)^2), max_abs = max|out-ref|.
// Grid: B=1, Z=Y=X=192, T=10, dx=20.
// ---------------------------------------------------------------------------

#define NN 192
#define VOL (NN * NN * NN)   // 7,077,888
#define TSTEPS 10

#define TX 32
#define TY 8
#define ZC 48
#define R  4

// Stencil coefficients (dx = 20 -> dx2 = 400)
#define C0 ((float)(-205.0 / 72.0 / 400.0))
#define C1 ((float)(8.0 / 5.0 / 400.0))
#define C2 ((float)(-1.0 / 5.0 / 400.0))
#define C3 ((float)(8.0 / 315.0 / 400.0))
#define C4 ((float)(-1.0 / 560.0 / 400.0))

// Scratch state buffers (allocation-free: __device__ globals)
__device__ float g_bufA[VOL];
__device__ float g_bufB[VOL];
__device__ double g_sum;
__device__ unsigned int g_maxbits;

__global__ void init_accum_kernel() {
    g_sum = 0.0;
    g_maxbits = 0u;
}

// One wave-equation timestep:
//   out[i] = 2*cur[i] - prev[i] + vp[i]*lap25(cur)[i] + src[i]
// prev may be nullptr (treated as zero). out may alias prev (thread-private idx).
__global__ void __launch_bounds__(TX * TY)
step_kernel(const float* __restrict__ cur,
            const float* __restrict__ prev,
            const float* __restrict__ vp,
            const float* __restrict__ src,
            float* __restrict__ out) {
    __shared__ float sp[TY + 2 * R][TX + 2 * R];  // 16 x 40 plane tile

    const int tx = threadIdx.x;
    const int ty = threadIdx.y;
    const int x0 = blockIdx.x * TX;
    const int y0 = blockIdx.y * TY;
    const int z0 = blockIdx.z * ZC;
    const int gx = x0 + tx;
    const int gy = y0 + ty;
    const int tid = ty * TX + tx;

    // Register queue of this thread's column: q[k] = cur plane (z - 4 + k)
    float q[2 * R + 1];
#pragma unroll
    for (int k = 0; k < 2 * R; k++) {
        int gz = z0 - R + k;
        q[k] = (gz >= 0 && gz < NN) ? cur[(gz * NN + gy) * NN + gx] : 0.0f;
    }

    for (int iz = 0; iz < ZC; iz++) {
        const int z = z0 + iz;

        __syncthreads();  // protect shared tile from previous iteration

        // Cooperative load of plane z tile (with radius-4 halo, zero outside)
#pragma unroll
        for (int i = tid; i < (TY + 2 * R) * (TX + 2 * R); i += TX * TY) {
            int sy = i / (TX + 2 * R);
            int sx = i - sy * (TX + 2 * R);
            int yy = y0 - R + sy;
            int xx = x0 - R + sx;
            float v = 0.0f;
            if (xx >= 0 && xx < NN && yy >= 0 && yy < NN)
                v = cur[(z * NN + yy) * NN + xx];
            sp[sy][sx] = v;
        }

        // Advance the z-queue head (plane z+4)
        {
            int zp = z + R;
            q[2 * R] = (zp < NN) ? cur[(zp * NN + gy) * NN + gx] : 0.0f;
        }

        __syncthreads();

        const int sx = tx + R;
        const int sy = ty + R;

        float lap = (3.0f * C0) * q[4];
        lap += C1 * (q[3] + q[5] + sp[sy][sx - 1] + sp[sy][sx + 1]
                               + sp[sy - 1][sx] + sp[sy + 1][sx]);
        lap += C2 * (q[2] + q[6] + sp[sy][sx - 2] + sp[sy][sx + 2]
                               + sp[sy - 2][sx] + sp[sy + 2][sx]);
        lap += C3 * (q[1] + q[7] + sp[sy][sx - 3] + sp[sy][sx + 3]
                               + sp[sy - 3][sx] + sp[sy + 3][sx]);
        lap += C4 * (q[0] + q[8] + sp[sy][sx - 4] + sp[sy][sx + 4]
                               + sp[sy - 4][sx] + sp[sy + 4][sx]);

        const int idx = (z * NN + gy) * NN + gx;
        const float pv = prev ? prev[idx] : 0.0f;
        out[idx] = 2.0f * q[4] - pv + vp[idx] * lap + src[idx];

        // Shift the queue
#pragma unroll
        for (int k = 0; k < 2 * R; k++) q[k] = q[k + 1];
    }
}

// Reduce: sum of squared error (double) + max abs error (float bits via atomicMax)
__global__ void __launch_bounds__(256)
reduce_kernel(const float* __restrict__ outp, const float* __restrict__ ref, int n) {
    double s = 0.0;
    float m = 0.0f;
    for (int i = blockIdx.x * blockDim.x + threadIdx.x; i < n;
         i += gridDim.x * blockDim.x) {
        float e = outp[i] - ref[i];
        s += (double)e * (double)e;
        m = fmaxf(m, fabsf(e));
    }
    // warp reduce
#pragma unroll
    for (int o = 16; o > 0; o >>= 1) {
        s += __shfl_down_sync(0xFFFFFFFFu, s, o);
        m = fmaxf(m, __shfl_down_sync(0xFFFFFFFFu, m, o));
    }
    __shared__ double ss[8];
    __shared__ float sm[8];
    int lane = threadIdx.x & 31;
    int w = threadIdx.x >> 5;
    if (lane == 0) { ss[w] = s; sm[w] = m; }
    __syncthreads();
    if (w == 0) {
        s = (lane < 8) ? ss[lane] : 0.0;
        m = (lane < 8) ? sm[lane] : 0.0f;
#pragma unroll
        for (int o = 4; o > 0; o >>= 1) {
            s += __shfl_down_sync(0xFFFFFFFFu, s, o);
            m = fmaxf(m, __shfl_down_sync(0xFFFFFFFFu, m, o));
        }
        if (lane == 0) {
            atomicAdd(&g_sum, s);
            atomicMax(&g_maxbits, __float_as_uint(m));
        }
    }
}

__global__ void finalize_kernel(float* d_out, int n) {
    d_out[0] = (float)(g_sum / (double)n);
    d_out[n + 1] = __uint_as_float(g_maxbits);
}

extern "C" void kernel_launch(void* const* d_in, const int* in_sizes, int n_in,
                              void* d_out, int out_size) {
    const float* vp  = (const float*)d_in[0];  // [1,192,192,192]
    const float* src = (const float*)d_in[1];  // [1,10,192,192,192]
    const float* ref = (const float*)d_in[2];  // [1,192,192,192]

    // Resolve device-global scratch addresses once (constant across calls)
    static float* bufA = nullptr;
    static float* bufB = nullptr;
    if (!bufA) {
        cudaGetSymbolAddress((void**)&bufA, g_bufA);
        cudaGetSymbolAddress((void**)&bufB, g_bufB);
    }

    const bool has_scalars = (out_size >= VOL + 2);
    float* outp = has_scalars ? ((float*)d_out + 1) : (float*)d_out;

    dim3 blk(TX, TY);
    dim3 grid(NN / TX, NN / TY, NN / ZC);

    init_accum_kernel<<<1, 1>>>();

    // Scan step t=0 gives cur = s_0 (prev = 0). Start from there, 9 real steps.
    const float* s0 = src;  // plane t=0

    // t=1: cur = s0 (input), prev = 0, out = A
    step_kernel<<<grid, blk>>>(s0, nullptr, vp, src + (size_t)1 * VOL, bufA);
    // t=2: cur = A, prev = s0 (input, read-only), out = B
    step_kernel<<<grid, blk>>>(bufA, s0, vp, src + (size_t)2 * VOL, bufB);
    // t=3..8: ping-pong, writing in-place over prev
    step_kernel<<<grid, blk>>>(bufB, bufA, vp, src + (size_t)3 * VOL, bufA);
    step_kernel<<<grid, blk>>>(bufA, bufB, vp, src + (size_t)4 * VOL, bufB);
    step_kernel<<<grid, blk>>>(bufB, bufA, vp, src + (size_t)5 * VOL, bufA);
    step_kernel<<<grid, blk>>>(bufA, bufB, vp, src + (size_t)6 * VOL, bufB);
    step_kernel<<<grid, blk>>>(bufB, bufA, vp, src + (size_t)7 * VOL, bufA);
    step_kernel<<<grid, blk>>>(bufA, bufB, vp, src + (size_t)8 * VOL, bufB);
    // t=9: final state straight into d_out's output slot
    step_kernel<<<grid, blk>>>(bufB, bufA, vp, src + (size_t)9 * VOL, outp);

    // Loss + max-abs reduction
    reduce_kernel<<<148 * 8, 256>>>(outp, ref, VOL);
    if (has_scalars) {
        finalize_kernel<<<1, 1>>>((float*)d_out, VOL);
    }
}

// round 2
// speedup vs baseline: 1.8006x; 1.8006x over previous
#include <cuda_runtime.h>
#include <cuda_bf16.h>
#include <math.h>

// ---------------------------------------------------------------------------
// 25-pt (radius-4, 3-axis) wave stencil, 10 scan steps (first is trivial),
// then loss = mean((out-ref)^2), max_abs = max|out-ref|.
// Grid: B=1, Z=Y=X=192, T=10, dx=20.
// R2: ZC=24 (full-occupancy single wave), double-buffered smem plane
// (1 barrier/iter + load/compute overlap), reduction fused into final step.
// ---------------------------------------------------------------------------

#define NN 192
#define VOL (NN * NN * NN)   // 7,077,888

#define TX 32
#define TY 8
#define ZC 24
#define R  4

#define TILE_H (TY + 2 * R)   // 16
#define TILE_W (TX + 2 * R)   // 40
#define TILE_ELEMS (TILE_H * TILE_W)  // 640

// Stencil coefficients (dx = 20 -> dx2 = 400)
#define C0 ((float)(-205.0 / 72.0 / 400.0))
#define C1 ((float)(8.0 / 5.0 / 400.0))
#define C2 ((float)(-1.0 / 5.0 / 400.0))
#define C3 ((float)(8.0 / 315.0 / 400.0))
#define C4 ((float)(-1.0 / 560.0 / 400.0))

// Scratch state buffers (allocation-free: __device__ globals)
__device__ float g_bufA[VOL];
__device__ float g_bufB[VOL];
__device__ double g_sum;
__device__ unsigned int g_maxbits;

__global__ void init_accum_kernel() {
    g_sum = 0.0;
    g_maxbits = 0u;
}

// One wave-equation timestep:
//   out[i] = 2*cur[i] - prev[i] + vp[i]*lap25(cur)[i] + src[i]
// prev may be nullptr (zero). out may alias prev (thread-private idx).
// If FINAL: also accumulate (out-ref)^2 and max|out-ref| into globals.
template <bool FINAL>
__global__ void __launch_bounds__(TX * TY, 8)
step_kernel(const float* __restrict__ cur,
            const float* __restrict__ prev,
            const float* __restrict__ vp,
            const float* __restrict__ src,
            float* __restrict__ out,
            const float* __restrict__ ref) {
    __shared__ float sp[2][TILE_H][TILE_W];

    const int tx = threadIdx.x;
    const int ty = threadIdx.y;
    const int x0 = blockIdx.x * TX;
    const int y0 = blockIdx.y * TY;
    const int z0 = blockIdx.z * ZC;
    const int gx = x0 + tx;
    const int gy = y0 + ty;
    const int tid = ty * TX + tx;

    // Precompute the (sy,sx) pairs this thread covers in the tile load,
    // and whether each is in-bounds (x/y bounds are z-invariant).
    int loff[3];   // byte offset into plane (row*NN + col), -1 if OOB/unused
    int lsidx[3];  // flat smem index
#pragma unroll
    for (int k = 0; k < 3; k++) {
        int i = tid + k * (TX * TY);
        if (i < TILE_ELEMS) {
            int sy = i / TILE_W;
            int sx = i - sy * TILE_W;
            int yy = y0 - R + sy;
            int xx = x0 - R + sx;
            lsidx[k] = i;
            loff[k] = (xx >= 0 && xx < NN && yy >= 0 && yy < NN) ? (yy * NN + xx) : -1;
        } else {
            lsidx[k] = -1;
            loff[k] = -1;
        }
    }

    // Register queue: q[k] = cur at plane (z - 4 + k)
    float q[2 * R + 1];
#pragma unroll
    for (int k = 0; k < 2 * R; k++) {
        int gz = z0 - R + k;
        q[k] = (gz >= 0 && gz < NN) ? __ldg(&cur[(gz * NN + gy) * NN + gx]) : 0.0f;
    }

    // Prime buffer 0 with plane z0
    {
        const float* plane = cur + (size_t)z0 * NN * NN;
        float* spf = &sp[0][0][0];
#pragma unroll
        for (int k = 0; k < 3; k++) {
            if (lsidx[k] >= 0)
                spf[lsidx[k]] = (loff[k] >= 0) ? __ldg(&plane[loff[k]]) : 0.0f;
        }
    }
    __syncthreads();

    double acc_s = 0.0;
    float acc_m = 0.0f;

    for (int iz = 0; iz < ZC; iz++) {
        const int z = z0 + iz;
        const int cb = iz & 1;
        const int nb = cb ^ 1;
        const int idx = (z * NN + gy) * NN + gx;

        // Issue next-plane tile loads into the other buffer (overlaps compute)
        if (iz + 1 < ZC) {
            const float* plane = cur + (size_t)(z + 1) * NN * NN;
            float* spf = &sp[nb][0][0];
#pragma unroll
            for (int k = 0; k < 3; k++) {
                if (lsidx[k] >= 0)
                    spf[lsidx[k]] = (loff[k] >= 0) ? __ldg(&plane[loff[k]]) : 0.0f;
            }
        }

        // Advance z-queue head (plane z+4) and fetch pointwise operands early
        {
            int zp = z + R;
            q[2 * R] = (zp < NN) ? __ldg(&cur[(zp * NN + gy) * NN + gx]) : 0.0f;
        }
        const float pv = prev ? __ldg(&prev[idx]) : 0.0f;
        const float vv = __ldg(&vp[idx]);
        const float sv = __ldg(&src[idx]);

        const int sx = tx + R;
        const int sy = ty + R;

        float lap = (3.0f * C0) * q[4];
        lap += C1 * (q[3] + q[5] + sp[cb][sy][sx - 1] + sp[cb][sy][sx + 1]
                               + sp[cb][sy - 1][sx] + sp[cb][sy + 1][sx]);
        lap += C2 * (q[2] + q[6] + sp[cb][sy][sx - 2] + sp[cb][sy][sx + 2]
                               + sp[cb][sy - 2][sx] + sp[cb][sy + 2][sx]);
        lap += C3 * (q[1] + q[7] + sp[cb][sy][sx - 3] + sp[cb][sy][sx + 3]
                               + sp[cb][sy - 3][sx] + sp[cb][sy + 3][sx]);
        lap += C4 * (q[0] + q[8] + sp[cb][sy][sx - 4] + sp[cb][sy][sx + 4]
                               + sp[cb][sy - 4][sx] + sp[cb][sy + 4][sx]);

        const float upd = 2.0f * q[4] - pv + vv * lap + sv;
        out[idx] = upd;

        if (FINAL) {
            float e = upd - __ldg(&ref[idx]);
            acc_s += (double)e * (double)e;
            acc_m = fmaxf(acc_m, fabsf(e));
        }

        // Shift the queue
#pragma unroll
        for (int k = 0; k < 2 * R; k++) q[k] = q[k + 1];

        __syncthreads();
    }

    if (FINAL) {
        // Warp then block reduction
#pragma unroll
        for (int o = 16; o > 0; o >>= 1) {
            acc_s += __shfl_down_sync(0xFFFFFFFFu, acc_s, o);
            acc_m = fmaxf(acc_m, __shfl_down_sync(0xFFFFFFFFu, acc_m, o));
        }
        __shared__ double ss[8];
        __shared__ float sm[8];
        int lane = tid & 31;
        int w = tid >> 5;
        if (lane == 0) { ss[w] = acc_s; sm[w] = acc_m; }
        __syncthreads();
        if (w == 0) {
            acc_s = (lane < 8) ? ss[lane] : 0.0;
            acc_m = (lane < 8) ? sm[lane] : 0.0f;
#pragma unroll
            for (int o = 4; o > 0; o >>= 1) {
                acc_s += __shfl_down_sync(0xFFFFFFFFu, acc_s, o);
                acc_m = fmaxf(acc_m, __shfl_down_sync(0xFFFFFFFFu, acc_m, o));
            }
            if (lane == 0) {
                atomicAdd(&g_sum, acc_s);
                atomicMax(&g_maxbits, __float_as_uint(acc_m));
            }
        }
    }
}

__global__ void finalize_kernel(float* d_out, int n) {
    d_out[0] = (float)(g_sum / (double)n);
    d_out[n + 1] = __uint_as_float(g_maxbits);
}

extern "C" void kernel_launch(void* const* d_in, const int* in_sizes, int n_in,
                              void* d_out, int out_size) {
    const float* vp  = (const float*)d_in[0];  // [1,192,192,192]
    const float* src = (const float*)d_in[1];  // [1,10,192,192,192]
    const float* ref = (const float*)d_in[2];  // [1,192,192,192]

    static float* bufA = nullptr;
    static float* bufB = nullptr;
    if (!bufA) {
        cudaGetSymbolAddress((void**)&bufA, g_bufA);
        cudaGetSymbolAddress((void**)&bufB, g_bufB);
    }

    const bool has_scalars = (out_size >= VOL + 2);
    float* outp = has_scalars ? ((float*)d_out + 1) : (float*)d_out;

    dim3 blk(TX, TY);
    dim3 grid(NN / TX, NN / TY, NN / ZC);

    init_accum_kernel<<<1, 1>>>();

    // Scan step t=0 gives cur = s_0 (prev = 0). Start from there, 9 real steps.
    const float* s0 = src;

    step_kernel<false><<<grid, blk>>>(s0,   nullptr, vp, src + (size_t)1 * VOL, bufA, nullptr);
    step_kernel<false><<<grid, blk>>>(bufA, s0,      vp, src + (size_t)2 * VOL, bufB, nullptr);
    step_kernel<false><<<grid, blk>>>(bufB, bufA,    vp, src + (size_t)3 * VOL, bufA, nullptr);
    step_kernel<false><<<grid, blk>>>(bufA, bufB,    vp, src + (size_t)4 * VOL, bufB, nullptr);
    step_kernel<false><<<grid, blk>>>(bufB, bufA,    vp, src + (size_t)5 * VOL, bufA, nullptr);
    step_kernel<false><<<grid, blk>>>(bufA, bufB,    vp, src + (size_t)6 * VOL, bufB, nullptr);
    step_kernel<false><<<grid, blk>>>(bufB, bufA,    vp, src + (size_t)7 * VOL, bufA, nullptr);
    step_kernel<false><<<grid, blk>>>(bufA, bufB,    vp, src + (size_t)8 * VOL, bufB, nullptr);
    // Final step: write into d_out and fuse the error reduction
    step_kernel<true><<<grid, blk>>>(bufB, bufA,     vp, src + (size_t)9 * VOL, outp, ref);

    if (has_scalars) {
        finalize_kernel<<<1, 1>>>((float*)d_out, VOL);
    }
}

// round 4
// speedup vs baseline: 2.6802x; 1.4886x over previous
#include <cuda_runtime.h>
#include <cuda_bf16.h>
#include <math.h>

// ---------------------------------------------------------------------------
// 25-pt (radius-4, 3-axis) wave stencil, 10 scan steps (first trivial),
// then loss = mean((out-ref)^2), max_abs = max|out-ref|.
// R4: float2 vectorization (2 x-points/thread), streaming loads for src/ref,
// double-buffered smem plane, fused reduction in final step.
// FINAL step uses scalar out-stores / ref-loads (d_out+1 is 4B-aligned only).
// ---------------------------------------------------------------------------

#define NN 192
#define PLANE (NN * NN)          // 36864
#define VOL (NN * NN * NN)       // 7,077,888

#define TXT 32                   // threads in x
#define VEC 2
#define SPANX (TXT * VEC)        // 64 x-points per block
#define TY 8
#define ZC 24
#define R  4

#define TILE_H (TY + 2 * R)              // 16
#define TILE_W (SPANX + 2 * R)           // 72 floats
#define TILE_W2 (TILE_W / 2)             // 36 float2
#define TILE_F2 (TILE_H * TILE_W2)       // 576 float2
#define NTHR (TXT * TY)                  // 256

// Stencil coefficients (dx = 20 -> dx2 = 400)
#define C0 ((float)(-205.0 / 72.0 / 400.0))
#define C1 ((float)(8.0 / 5.0 / 400.0))
#define C2 ((float)(-1.0 / 5.0 / 400.0))
#define C3 ((float)(8.0 / 315.0 / 400.0))
#define C4 ((float)(-1.0 / 560.0 / 400.0))

__device__ float g_bufA[VOL];
__device__ float g_bufB[VOL];
__device__ double g_sum;
__device__ unsigned int g_maxbits;

__global__ void init_accum_kernel() {
    g_sum = 0.0;
    g_maxbits = 0u;
}

__device__ __forceinline__ float2 ldg2(const float* p) {
    return *reinterpret_cast<const float2*>(p);
}
__device__ __forceinline__ float2 ldcs2(const float* p) {
    float2 v;
    asm volatile("ld.global.cs.v2.f32 {%0,%1}, [%2];"
                 : "=f"(v.x), "=f"(v.y) : "l"(p));
    return v;
}
__device__ __forceinline__ float ldcs1(const float* p) {
    float v;
    asm volatile("ld.global.cs.f32 %0, [%1];" : "=f"(v) : "l"(p));
    return v;
}

// out[i] = 2*cur[i] - prev[i] + vp[i]*lap25(cur)[i] + src[i]
// prev may be nullptr (zero). out may alias prev (thread-private idx).
// FINAL: out/ref may be only 4B-aligned -> scalar accesses; fused reduction.
template <bool FINAL>
__global__ void __launch_bounds__(NTHR, 4)
step_kernel(const float* __restrict__ cur,
            const float* __restrict__ prev,
            const float* __restrict__ vp,
            const float* __restrict__ src,
            float* __restrict__ out,
            const float* __restrict__ ref) {
    __shared__ float sp[2][TILE_H][TILE_W];

    const int tx = threadIdx.x;
    const int ty = threadIdx.y;
    const int x0 = blockIdx.x * SPANX;
    const int y0 = blockIdx.y * TY;
    const int z0 = blockIdx.z * ZC;
    const int gx = x0 + 2 * tx;          // even -> float2 aligned
    const int gy = y0 + ty;
    const int tid = ty * TXT + tx;

    // Cooperative tile-load slots (float2 granularity), z-invariant bounds.
    int sidx[3];   // float index into tile plane, -1 unused
    int goff[3];   // float index into global plane, -1 OOB
#pragma unroll
    for (int k = 0; k < 3; k++) {
        int i = tid + k * NTHR;
        if (i < TILE_F2) {
            int sy = i / TILE_W2;
            int sxx = i - sy * TILE_W2;
            int yy = y0 - R + sy;
            int xx = x0 - R + 2 * sxx;   // pair fully in or fully out
            sidx[k] = sy * TILE_W + 2 * sxx;
            goff[k] = (xx >= 0 && xx < NN && yy >= 0 && yy < NN) ? (yy * NN + xx) : -1;
        } else {
            sidx[k] = -1;
            goff[k] = -1;
        }
    }

    // Register queue: q[k] = cur at plane (z - 4 + k), this thread's 2 points
    float2 q[2 * R + 1];
#pragma unroll
    for (int k = 0; k < 2 * R; k++) {
        int gz = z0 - R + k;
        q[k] = (gz >= 0 && gz < NN) ? ldg2(&cur[(size_t)gz * PLANE + gy * NN + gx])
                                    : make_float2(0.f, 0.f);
    }

    // Prime buffer 0 with plane z0
    {
        const float* plane = cur + (size_t)z0 * PLANE;
#pragma unroll
        for (int k = 0; k < 3; k++) {
            if (sidx[k] >= 0) {
                float2 v = (goff[k] >= 0) ? ldg2(&plane[goff[k]]) : make_float2(0.f, 0.f);
                *reinterpret_cast<float2*>(&sp[0][0][0] + sidx[k]) = v;
            }
        }
    }
    __syncthreads();

    double acc_s = 0.0;
    float acc_m = 0.0f;

    const bool hasprev = (prev != nullptr);
    const int sx = R + 2 * tx;   // even
    const int syc = ty + R;

#pragma unroll 2
    for (int iz = 0; iz < ZC; iz++) {
        const int z = z0 + iz;
        const int cb = iz & 1;
        const int nb = cb ^ 1;
        const int idx = z * PLANE + gy * NN + gx;

        // Next-plane tile loads into the other buffer (overlap with compute)
        if (iz + 1 < ZC) {
            const float* plane = cur + (size_t)(z + 1) * PLANE;
#pragma unroll
            for (int k = 0; k < 3; k++) {
                if (sidx[k] >= 0) {
                    float2 v = (goff[k] >= 0) ? ldg2(&plane[goff[k]]) : make_float2(0.f, 0.f);
                    *reinterpret_cast<float2*>(&sp[nb][0][0] + sidx[k]) = v;
                }
            }
        }

        // Advance z-queue head (plane z+4); pointwise operands early
        {
            int zp = z + R;
            q[2 * R] = (zp < NN) ? ldg2(&cur[(size_t)zp * PLANE + gy * NN + gx])
                                 : make_float2(0.f, 0.f);
        }
        const float2 pv = hasprev ? ldg2(&prev[idx]) : make_float2(0.f, 0.f);
        const float2 vv = ldg2(&vp[idx]);
        const float2 sv = ldcs2(&src[idx]);

        // x-row: 10 floats sp[cb][syc][sx-4 .. sx+5] via 5 aligned float2
        float xs[10];
#pragma unroll
        for (int j = 0; j < 5; j++) {
            float2 t = *reinterpret_cast<const float2*>(&sp[cb][syc][sx - 4 + 2 * j]);
            xs[2 * j] = t.x;
            xs[2 * j + 1] = t.y;
        }

        float lap_x = (3.0f * C0) * q[4].x;
        float lap_y = (3.0f * C0) * q[4].y;

        {
            float2 ym = *reinterpret_cast<const float2*>(&sp[cb][syc - 1][sx]);
            float2 yp = *reinterpret_cast<const float2*>(&sp[cb][syc + 1][sx]);
            lap_x += C1 * (q[3].x + q[5].x + ym.x + yp.x + xs[3] + xs[5]);
            lap_y += C1 * (q[3].y + q[5].y + ym.y + yp.y + xs[4] + xs[6]);
        }
        {
            float2 ym = *reinterpret_cast<const float2*>(&sp[cb][syc - 2][sx]);
            float2 yp = *reinterpret_cast<const float2*>(&sp[cb][syc + 2][sx]);
            lap_x += C2 * (q[2].x + q[6].x + ym.x + yp.x + xs[2] + xs[6]);
            lap_y += C2 * (q[2].y + q[6].y + ym.y + yp.y + xs[3] + xs[7]);
        }
        {
            float2 ym = *reinterpret_cast<const float2*>(&sp[cb][syc - 3][sx]);
            float2 yp = *reinterpret_cast<const float2*>(&sp[cb][syc + 3][sx]);
            lap_x += C3 * (q[1].x + q[7].x + ym.x + yp.x + xs[1] + xs[7]);
            lap_y += C3 * (q[1].y + q[7].y + ym.y + yp.y + xs[2] + xs[8]);
        }
        {
            float2 ym = *reinterpret_cast<const float2*>(&sp[cb][syc - 4][sx]);
            float2 yp = *reinterpret_cast<const float2*>(&sp[cb][syc + 4][sx]);
            lap_x += C4 * (q[0].x + q[8].x + ym.x + yp.x + xs[0] + xs[8]);
            lap_y += C4 * (q[0].y + q[8].y + ym.y + yp.y + xs[1] + xs[9]);
        }

        float2 upd;
        upd.x = 2.0f * q[4].x - pv.x + vv.x * lap_x + sv.x;
        upd.y = 2.0f * q[4].y - pv.y + vv.y * lap_y + sv.y;

        if (FINAL) {
            // out/ref only 4B-aligned: scalar stores/loads
            out[idx] = upd.x;
            out[idx + 1] = upd.y;
            float rx = ldcs1(&ref[idx]);
            float ry = ldcs1(&ref[idx + 1]);
            float ex = upd.x - rx;
            float ey = upd.y - ry;
            acc_s += (double)ex * (double)ex + (double)ey * (double)ey;
            acc_m = fmaxf(acc_m, fmaxf(fabsf(ex), fabsf(ey)));
        } else {
            *reinterpret_cast<float2*>(&out[idx]) = upd;
        }

        // Shift queue
#pragma unroll
        for (int k = 0; k < 2 * R; k++) q[k] = q[k + 1];

        __syncthreads();
    }

    if (FINAL) {
#pragma unroll
        for (int o = 16; o > 0; o >>= 1) {
            acc_s += __shfl_down_sync(0xFFFFFFFFu, acc_s, o);
            acc_m = fmaxf(acc_m, __shfl_down_sync(0xFFFFFFFFu, acc_m, o));
        }
        __shared__ double ss[8];
        __shared__ float sm[8];
        int lane = tid & 31;
        int w = tid >> 5;
        if (lane == 0) { ss[w] = acc_s; sm[w] = acc_m; }
        __syncthreads();
        if (w == 0) {
            acc_s = (lane < 8) ? ss[lane] : 0.0;
            acc_m = (lane < 8) ? sm[lane] : 0.0f;
#pragma unroll
            for (int o = 4; o > 0; o >>= 1) {
                acc_s += __shfl_down_sync(0xFFFFFFFFu, acc_s, o);
                acc_m = fmaxf(acc_m, __shfl_down_sync(0xFFFFFFFFu, acc_m, o));
            }
            if (lane == 0) {
                atomicAdd(&g_sum, acc_s);
                atomicMax(&g_maxbits, __float_as_uint(acc_m));
            }
        }
    }
}

__global__ void finalize_kernel(float* d_out, int n) {
    d_out[0] = (float)(g_sum / (double)n);
    d_out[n + 1] = __uint_as_float(g_maxbits);
}

extern "C" void kernel_launch(void* const* d_in, const int* in_sizes, int n_in,
                              void* d_out, int out_size) {
    const float* vp  = (const float*)d_in[0];  // [1,192,192,192]
    const float* src = (const float*)d_in[1];  // [1,10,192,192,192]
    const float* ref = (const float*)d_in[2];  // [1,192,192,192]

    static float* bufA = nullptr;
    static float* bufB = nullptr;
    if (!bufA) {
        cudaGetSymbolAddress((void**)&bufA, g_bufA);
        cudaGetSymbolAddress((void**)&bufB, g_bufB);
    }

    const bool has_scalars = (out_size >= VOL + 2);
    float* outp = has_scalars ? ((float*)d_out + 1) : (float*)d_out;

    dim3 blk(TXT, TY);
    dim3 grid(NN / SPANX, NN / TY, NN / ZC);   // (3, 24, 8) = 576 blocks

    init_accum_kernel<<<1, 1>>>();

    // Scan step t=0 gives cur = s_0 (prev = 0). Start there, 9 real steps.
    const float* s0 = src;

    step_kernel<false><<<grid, blk>>>(s0,   nullptr, vp, src + (size_t)1 * VOL, bufA, nullptr);
    step_kernel<false><<<grid, blk>>>(bufA, s0,      vp, src + (size_t)2 * VOL, bufB, nullptr);
    step_kernel<false><<<grid, blk>>>(bufB, bufA,    vp, src + (size_t)3 * VOL, bufA, nullptr);
    step_kernel<false><<<grid, blk>>>(bufA, bufB,    vp, src + (size_t)4 * VOL, bufB, nullptr);
    step_kernel<false><<<grid, blk>>>(bufB, bufA,    vp, src + (size_t)5 * VOL, bufA, nullptr);
    step_kernel<false><<<grid, blk>>>(bufA, bufB,    vp, src + (size_t)6 * VOL, bufB, nullptr);
    step_kernel<false><<<grid, blk>>>(bufB, bufA,    vp, src + (size_t)7 * VOL, bufA, nullptr);
    step_kernel<false><<<grid, blk>>>(bufA, bufB,    vp, src + (size_t)8 * VOL, bufB, nullptr);
    step_kernel<true><<<grid, blk>>>(bufB, bufA,     vp, src + (size_t)9 * VOL, outp, ref);

    if (has_scalars) {
        finalize_kernel<<<1, 1>>>((float*)d_out, VOL);
    }
}

// round 5
// speedup vs baseline: 2.8305x; 1.0561x over previous
#include <cuda_runtime.h>
#include <cuda_bf16.h>
#include <math.h>

// ---------------------------------------------------------------------------
// 25-pt (radius-4, 3-axis) wave stencil, 10 scan steps (first trivial),
// then loss = mean((out-ref)^2), max_abs = max|out-ref|.
// R5: statically-disjoint double smem buffers (spA/spB, body unrolled x2) so
// fill-STS never orders before consume-LDS; reg diet + launch_bounds(256,6);
// ZC=16 -> 864 blocks = one ~75%-occupancy wave.
// ---------------------------------------------------------------------------

#define NN 192
#define PLANE (NN * NN)
#define VOL (NN * NN * NN)

#define TXT 32
#define SPANX 64
#define TY 8
#define ZC 16
#define R  4

#define TILE_H (TY + 2 * R)              // 16
#define TILE_W (SPANX + 2 * R)           // 72
#define TILE_W2 (TILE_W / 2)             // 36
#define TILE_F2 (TILE_H * TILE_W2)       // 576
#define NTHR (TXT * TY)                  // 256

#define C0 ((float)(-205.0 / 72.0 / 400.0))
#define C1 ((float)(8.0 / 5.0 / 400.0))
#define C2 ((float)(-1.0 / 5.0 / 400.0))
#define C3 ((float)(8.0 / 315.0 / 400.0))
#define C4 ((float)(-1.0 / 560.0 / 400.0))

__device__ float g_bufA[VOL];
__device__ float g_bufB[VOL];
__device__ double g_sum;
__device__ unsigned int g_maxbits;

__global__ void init_accum_kernel() {
    g_sum = 0.0;
    g_maxbits = 0u;
}

__device__ __forceinline__ float2 ldg2(const float* p) {
    return *reinterpret_cast<const float2*>(p);
}
__device__ __forceinline__ float2 ldcs2(const float* p) {
    float2 v;
    asm volatile("ld.global.cs.v2.f32 {%0,%1}, [%2];"
                 : "=f"(v.x), "=f"(v.y) : "l"(p));
    return v;
}
__device__ __forceinline__ float ldcs1(const float* p) {
    float v;
    asm volatile("ld.global.cs.f32 %0, [%1];" : "=f"(v) : "l"(p));
    return v;
}

template <bool FINAL>
struct StepCtx {
    const float* cur;
    const float* prev;
    const float* vp;
    const float* src;
    float* out;
    const float* ref;
};

template <bool FINAL>
__device__ __forceinline__ void plane_body(
    const StepCtx<FINAL>& c,
    const float (&consume)[TILE_H][TILE_W],
    float (&fill)[TILE_H][TILE_W],
    int z, bool do_fill, bool hasprev,
    const int* goff, const int* sidx,
    int col,
    float2 q[9],
    int sx, int syc,
    double& acc_s, float& acc_m) {

    const int zoff = z * PLANE;
    const int idx = zoff + col;

    // ---- issue all global loads first (max MLP) ----
    float2 f0 = make_float2(0.f, 0.f), f1 = f0, f2 = f0;
    if (do_fill) {
        const float* plane = c.cur + zoff + PLANE;
        if (goff[0] >= 0) f0 = ldg2(&plane[goff[0]]);
        if (goff[1] >= 0) f1 = ldg2(&plane[goff[1]]);
        if (sidx[2] >= 0 && goff[2] >= 0) f2 = ldg2(&plane[goff[2]]);
    }
    {
        int zp = z + R;
        q[8] = (zp < NN) ? ldg2(&c.cur[zp * PLANE + col]) : make_float2(0.f, 0.f);
    }
    const float2 pv = hasprev ? ldg2(&c.prev[idx]) : make_float2(0.f, 0.f);
    const float2 vv = ldg2(&c.vp[idx]);
    const float2 sv = ldcs2(&c.src[idx]);

    // ---- x-row taps: xs[j] = consume[syc][sx-4+j], j=0..9 (5 aligned LDS.64)
    float xs[10];
#pragma unroll
    for (int j = 0; j < 5; j++) {
        float2 t = *reinterpret_cast<const float2*>(&consume[syc][sx - 4 + 2 * j]);
        xs[2 * j] = t.x;
        xs[2 * j + 1] = t.y;
    }

    float lap_x = (3.0f * C0) * q[4].x;
    float lap_y = (3.0f * C0) * q[4].y;
    {
        float2 ym = *reinterpret_cast<const float2*>(&consume[syc - 1][sx]);
        float2 yp = *reinterpret_cast<const float2*>(&consume[syc + 1][sx]);
        lap_x += C1 * (q[3].x + q[5].x + ym.x + yp.x + xs[3] + xs[5]);
        lap_y += C1 * (q[3].y + q[5].y + ym.y + yp.y + xs[4] + xs[6]);
    }
    {
        float2 ym = *reinterpret_cast<const float2*>(&consume[syc - 2][sx]);
        float2 yp = *reinterpret_cast<const float2*>(&consume[syc + 2][sx]);
        lap_x += C2 * (q[2].x + q[6].x + ym.x + yp.x + xs[2] + xs[6]);
        lap_y += C2 * (q[2].y + q[6].y + ym.y + yp.y + xs[3] + xs[7]);
    }
    {
        float2 ym = *reinterpret_cast<const float2*>(&consume[syc - 3][sx]);
        float2 yp = *reinterpret_cast<const float2*>(&consume[syc + 3][sx]);
        lap_x += C3 * (q[1].x + q[7].x + ym.x + yp.x + xs[1] + xs[7]);
        lap_y += C3 * (q[1].y + q[7].y + ym.y + yp.y + xs[2] + xs[8]);
    }
    {
        float2 ym = *reinterpret_cast<const float2*>(&consume[syc - 4][sx]);
        float2 yp = *reinterpret_cast<const float2*>(&consume[syc + 4][sx]);
        lap_x += C4 * (q[0].x + q[8].x + ym.x + yp.x + xs[0] + xs[8]);
        lap_y += C4 * (q[0].y + q[8].y + ym.y + yp.y + xs[1] + xs[9]);
    }

    float2 upd;
    upd.x = 2.0f * q[4].x - pv.x + vv.x * lap_x + sv.x;
    upd.y = 2.0f * q[4].y - pv.y + vv.y * lap_y + sv.y;

    if (FINAL) {
        c.out[idx] = upd.x;
        c.out[idx + 1] = upd.y;
        float ex = upd.x - ldcs1(&c.ref[idx]);
        float ey = upd.y - ldcs1(&c.ref[idx + 1]);
        acc_s += (double)ex * (double)ex + (double)ey * (double)ey;
        acc_m = fmaxf(acc_m, fmaxf(fabsf(ex), fabsf(ey)));
    } else {
        *reinterpret_cast<float2*>(&c.out[idx]) = upd;
    }

    // ---- commit staged fill data (STS to the OTHER buffer), then barrier ----
    if (do_fill) {
        float* fb = &fill[0][0];
        *reinterpret_cast<float2*>(fb + sidx[0]) = f0;
        *reinterpret_cast<float2*>(fb + sidx[1]) = f1;
        if (sidx[2] >= 0) *reinterpret_cast<float2*>(fb + sidx[2]) = f2;
    }

#pragma unroll
    for (int k = 0; k < 8; k++) q[k] = q[k + 1];

    __syncthreads();
}

template <bool FINAL>
__global__ void __launch_bounds__(NTHR, 6)
step_kernel(const float* __restrict__ cur,
            const float* __restrict__ prev,
            const float* __restrict__ vp,
            const float* __restrict__ src,
            float* __restrict__ out,
            const float* __restrict__ ref) {
    __shared__ float spA[TILE_H][TILE_W];
    __shared__ float spB[TILE_H][TILE_W];

    const int tx = threadIdx.x;
    const int ty = threadIdx.y;
    const int x0 = blockIdx.x * SPANX;
    const int y0 = blockIdx.y * TY;
    const int z0 = blockIdx.z * ZC;
    const int gx = x0 + 2 * tx;
    const int gy = y0 + ty;
    const int tid = ty * TXT + tx;
    const int col = gy * NN + gx;

    int goff[3], sidx[3];
#pragma unroll
    for (int k = 0; k < 3; k++) {
        int i = tid + k * NTHR;
        if (i < TILE_F2) {
            int sy = i / TILE_W2;
            int sxx = i - sy * TILE_W2;
            int yy = y0 - R + sy;
            int xx = x0 - R + 2 * sxx;
            sidx[k] = sy * TILE_W + 2 * sxx;
            goff[k] = (xx >= 0 && xx < NN && yy >= 0 && yy < NN) ? (yy * NN + xx) : -1;
        } else {
            sidx[k] = -1;
            goff[k] = -1;
        }
    }

    float2 q[9];
#pragma unroll
    for (int k = 0; k < 8; k++) {
        int gz = z0 - R + k;
        q[k] = (gz >= 0) ? ldg2(&cur[gz * PLANE + col]) : make_float2(0.f, 0.f);
    }

    {
        const float* plane = cur + z0 * PLANE;
        float* fb = &spA[0][0];
#pragma unroll
        for (int k = 0; k < 3; k++) {
            if (sidx[k] >= 0) {
                float2 v = (goff[k] >= 0) ? ldg2(&plane[goff[k]]) : make_float2(0.f, 0.f);
                *reinterpret_cast<float2*>(fb + sidx[k]) = v;
            }
        }
    }
    __syncthreads();

    StepCtx<FINAL> c{cur, prev, vp, src, out, ref};
    const bool hasprev = (prev != nullptr);
    const int sx = R + 2 * tx;
    const int syc = ty + R;

    double acc_s = 0.0;
    float acc_m = 0.0f;

#pragma unroll 1
    for (int iz = 0; iz < ZC; iz += 2) {
        plane_body<FINAL>(c, spA, spB, z0 + iz, true, hasprev,
                          goff, sidx, col, q, sx, syc, acc_s, acc_m);
        plane_body<FINAL>(c, spB, spA, z0 + iz + 1, (iz + 2 < ZC), hasprev,
                          goff, sidx, col, q, sx, syc, acc_s, acc_m);
    }

    if (FINAL) {
#pragma unroll
        for (int o = 16; o > 0; o >>= 1) {
            acc_s += __shfl_down_sync(0xFFFFFFFFu, acc_s, o);
            acc_m = fmaxf(acc_m, __shfl_down_sync(0xFFFFFFFFu, acc_m, o));
        }
        __shared__ double ss[8];
        __shared__ float sm[8];
        int lane = tid & 31;
        int w = tid >> 5;
        if (lane == 0) { ss[w] = acc_s; sm[w] = acc_m; }
        __syncthreads();
        if (w == 0) {
            acc_s = (lane < 8) ? ss[lane] : 0.0;
            acc_m = (lane < 8) ? sm[lane] : 0.0f;
#pragma unroll
            for (int o = 4; o > 0; o >>= 1) {
                acc_s += __shfl_down_sync(0xFFFFFFFFu, acc_s, o);
                acc_m = fmaxf(acc_m, __shfl_down_sync(0xFFFFFFFFu, acc_m, o));
            }
            if (lane == 0) {
                atomicAdd(&g_sum, acc_s);
                atomicMax(&g_maxbits, __float_as_uint(acc_m));
            }
        }
    }
}

__global__ void finalize_kernel(float* d_out, int n) {
    d_out[0] = (float)(g_sum / (double)n);
    d_out[n + 1] = __uint_as_float(g_maxbits);
}

extern "C" void kernel_launch(void* const* d_in, const int* in_sizes, int n_in,
                              void* d_out, int out_size) {
    const float* vp  = (const float*)d_in[0];
    const float* src = (const float*)d_in[1];
    const float* ref = (const float*)d_in[2];

    static float* bufA = nullptr;
    static float* bufB = nullptr;
    if (!bufA) {
        cudaGetSymbolAddress((void**)&bufA, g_bufA);
        cudaGetSymbolAddress((void**)&bufB, g_bufB);
    }

    const bool has_scalars = (out_size >= VOL + 2);
    float* outp = has_scalars ? ((float*)d_out + 1) : (float*)d_out;

    dim3 blk(TXT, TY);
    dim3 grid(NN / SPANX, NN / TY, NN / ZC);   // (3, 24, 12) = 864 blocks

    init_accum_kernel<<<1, 1>>>();

    const float* s0 = src;

    step_kernel<false><<<grid, blk>>>(s0,   nullptr, vp, src + (size_t)1 * VOL, bufA, nullptr);
    step_kernel<false><<<grid, blk>>>(bufA, s0,      vp, src + (size_t)2 * VOL, bufB, nullptr);
    step_kernel<false><<<grid, blk>>>(bufB, bufA,    vp, src + (size_t)3 * VOL, bufA, nullptr);
    step_kernel<false><<<grid, blk>>>(bufA, bufB,    vp, src + (size_t)4 * VOL, bufB, nullptr);
    step_kernel<false><<<grid, blk>>>(bufB, bufA,    vp, src + (size_t)5 * VOL, bufA, nullptr);
    step_kernel<false><<<grid, blk>>>(bufA, bufB,    vp, src + (size_t)6 * VOL, bufB, nullptr);
    step_kernel<false><<<grid, blk>>>(bufB, bufA,    vp, src + (size_t)7 * VOL, bufA, nullptr);
    step_kernel<false><<<grid, blk>>>(bufA, bufB,    vp, src + (size_t)8 * VOL, bufB, nullptr);
    step_kernel<true><<<grid, blk>>>(bufB, bufA,     vp, src + (size_t)9 * VOL, outp, ref);

    if (has_scalars) {
        finalize_kernel<<<1, 1>>>((float*)d_out, VOL);
    }
}

// round 6
// speedup vs baseline: 3.3448x; 1.1817x over previous
#include <cuda_runtime.h>
#include <cuda_bf16.h>
#include <math.h>

// ---------------------------------------------------------------------------
// 25-pt (radius-4, 3-axis) wave stencil, 10 scan steps (first trivial),
// then loss = mean((out-ref)^2), max_abs = max|out-ref|.
// R6: float4 (4 x-points/thread). LDS.128/LDG.128 everywhere, static A/B smem
// buffers, streaming src/ref, fused reduction. Block 128 thr, ZC=16.
// ---------------------------------------------------------------------------

#define NN 192
#define PLANE (NN * NN)
#define VOL (NN * NN * NN)

#define TXT 16
#define TY 8
#define NTHR (TXT * TY)          // 128
#define SPANX (TXT * 4)          // 64 x-points per block
#define ZC 16
#define R  4

#define TILE_H (TY + 2 * R)      // 16
#define TILE_WU (SPANX + 2 * R)  // 72 floats used
#define TILE_W 80                // padded: 320B row stride (16B multiple)
#define FW4 (TILE_WU / 4)        // 18 float4 per row
#define NSLOT (TILE_H * FW4)     // 288 fill slots

#define C0 ((float)(-205.0 / 72.0 / 400.0))
#define C1 ((float)(8.0 / 5.0 / 400.0))
#define C2 ((float)(-1.0 / 5.0 / 400.0))
#define C3 ((float)(8.0 / 315.0 / 400.0))
#define C4 ((float)(-1.0 / 560.0 / 400.0))

__device__ float g_bufA[VOL];
__device__ float g_bufB[VOL];
__device__ double g_sum;
__device__ unsigned int g_maxbits;

__global__ void init_accum_kernel() {
    g_sum = 0.0;
    g_maxbits = 0u;
}

__device__ __forceinline__ float4 ldg4(const float* p) {
    return *reinterpret_cast<const float4*>(p);
}
__device__ __forceinline__ float4 ldcs4(const float* p) {
    float4 v;
    asm volatile("ld.global.cs.v4.f32 {%0,%1,%2,%3}, [%4];"
                 : "=f"(v.x), "=f"(v.y), "=f"(v.z), "=f"(v.w) : "l"(p));
    return v;
}
__device__ __forceinline__ float ldcs1(const float* p) {
    float v;
    asm volatile("ld.global.cs.f32 %0, [%1];" : "=f"(v) : "l"(p));
    return v;
}

template <bool FINAL>
struct StepCtx {
    const float* cur;
    const float* prev;
    const float* vp;
    const float* src;
    float* out;
    const float* ref;
};

// Per-point laplacian combine helper: given 4-wide z/y taps and xs row.
template <bool FINAL>
__device__ __forceinline__ void plane_body(
    const StepCtx<FINAL>& c,
    const float (&consume)[TILE_H][TILE_W],
    float (&fill)[TILE_H][TILE_W],
    int z, bool do_fill, bool hasprev,
    const int* goff, const int* sidx,
    int col,
    float4 q[9],
    int sx, int syc,
    double& acc_s, float& acc_m) {

    const int zoff = z * PLANE;
    const int idx = zoff + col;

    // ---- issue all global loads first (max MLP) ----
    float4 f0 = make_float4(0.f, 0.f, 0.f, 0.f), f1 = f0, f2 = f0;
    if (do_fill) {
        const float* plane = c.cur + zoff + PLANE;
        if (goff[0] >= 0) f0 = ldg4(&plane[goff[0]]);
        if (goff[1] >= 0) f1 = ldg4(&plane[goff[1]]);
        if (sidx[2] >= 0 && goff[2] >= 0) f2 = ldg4(&plane[goff[2]]);
    }
    {
        int zp = z + R;
        q[8] = (zp < NN) ? ldg4(&c.cur[zp * PLANE + col])
                         : make_float4(0.f, 0.f, 0.f, 0.f);
    }
    const float4 pv = hasprev ? ldg4(&c.prev[idx]) : make_float4(0.f, 0.f, 0.f, 0.f);
    const float4 vv = ldg4(&c.vp[idx]);
    const float4 sv = ldcs4(&c.src[idx]);

    // ---- x-row taps: xs[j] = consume[syc][sx-4+j], j=0..11 (3 LDS.128) ----
    float xs[12];
#pragma unroll
    for (int j = 0; j < 3; j++) {
        float4 t = *reinterpret_cast<const float4*>(&consume[syc][sx - 4 + 4 * j]);
        xs[4 * j + 0] = t.x;
        xs[4 * j + 1] = t.y;
        xs[4 * j + 2] = t.z;
        xs[4 * j + 3] = t.w;
    }

    float lap[4];
    {
        const float* q4 = &q[4].x;
#pragma unroll
        for (int p = 0; p < 4; p++) lap[p] = (3.0f * C0) * q4[p];
    }
    {
        float4 ym = *reinterpret_cast<const float4*>(&consume[syc - 1][sx]);
        float4 yp = *reinterpret_cast<const float4*>(&consume[syc + 1][sx]);
        const float* q3 = &q[3].x;
        const float* q5 = &q[5].x;
        const float* a = &ym.x;
        const float* b = &yp.x;
#pragma unroll
        for (int p = 0; p < 4; p++)
            lap[p] += C1 * (q3[p] + q5[p] + a[p] + b[p] + xs[p + 3] + xs[p + 5]);
    }
    {
        float4 ym = *reinterpret_cast<const float4*>(&consume[syc - 2][sx]);
        float4 yp = *reinterpret_cast<const float4*>(&consume[syc + 2][sx]);
        const float* q2 = &q[2].x;
        const float* q6 = &q[6].x;
        const float* a = &ym.x;
        const float* b = &yp.x;
#pragma unroll
        for (int p = 0; p < 4; p++)
            lap[p] += C2 * (q2[p] + q6[p] + a[p] + b[p] + xs[p + 2] + xs[p + 6]);
    }
    {
        float4 ym = *reinterpret_cast<const float4*>(&consume[syc - 3][sx]);
        float4 yp = *reinterpret_cast<const float4*>(&consume[syc + 3][sx]);
        const float* q1 = &q[1].x;
        const float* q7 = &q[7].x;
        const float* a = &ym.x;
        const float* b = &yp.x;
#pragma unroll
        for (int p = 0; p < 4; p++)
            lap[p] += C3 * (q1[p] + q7[p] + a[p] + b[p] + xs[p + 1] + xs[p + 7]);
    }
    {
        float4 ym = *reinterpret_cast<const float4*>(&consume[syc - 4][sx]);
        float4 yp = *reinterpret_cast<const float4*>(&consume[syc + 4][sx]);
        const float* q0 = &q[0].x;
        const float* q8 = &q[8].x;
        const float* a = &ym.x;
        const float* b = &yp.x;
#pragma unroll
        for (int p = 0; p < 4; p++)
            lap[p] += C4 * (q0[p] + q8[p] + a[p] + b[p] + xs[p] + xs[p + 8]);
    }

    float4 upd;
    {
        const float* q4 = &q[4].x;
        const float* pvp = &pv.x;
        const float* vvp = &vv.x;
        const float* svp = &sv.x;
        float* u = &upd.x;
#pragma unroll
        for (int p = 0; p < 4; p++)
            u[p] = 2.0f * q4[p] - pvp[p] + vvp[p] * lap[p] + svp[p];
    }

    if (FINAL) {
        const float* u = &upd.x;
#pragma unroll
        for (int p = 0; p < 4; p++) {
            c.out[idx + p] = u[p];
            float e = u[p] - ldcs1(&c.ref[idx + p]);
            acc_s += (double)e * (double)e;
            acc_m = fmaxf(acc_m, fabsf(e));
        }
    } else {
        *reinterpret_cast<float4*>(&c.out[idx]) = upd;
    }

    // ---- commit staged fill (STS to OTHER buffer), then barrier ----
    if (do_fill) {
        float* fb = &fill[0][0];
        *reinterpret_cast<float4*>(fb + sidx[0]) = f0;
        *reinterpret_cast<float4*>(fb + sidx[1]) = f1;
        if (sidx[2] >= 0) *reinterpret_cast<float4*>(fb + sidx[2]) = f2;
    }

#pragma unroll
    for (int k = 0; k < 8; k++) q[k] = q[k + 1];

    __syncthreads();
}

template <bool FINAL>
__global__ void __launch_bounds__(NTHR, 6)
step_kernel(const float* __restrict__ cur,
            const float* __restrict__ prev,
            const float* __restrict__ vp,
            const float* __restrict__ src,
            float* __restrict__ out,
            const float* __restrict__ ref) {
    __shared__ float spA[TILE_H][TILE_W];
    __shared__ float spB[TILE_H][TILE_W];

    const int tx = threadIdx.x;
    const int ty = threadIdx.y;
    const int x0 = blockIdx.x * SPANX;
    const int y0 = blockIdx.y * TY;
    const int z0 = blockIdx.z * ZC;
    const int gx = x0 + 4 * tx;
    const int gy = y0 + ty;
    const int tid = ty * TXT + tx;
    const int col = gy * NN + gx;

    // Cooperative fill slots: NSLOT=288 float4 over 128 threads -> 3 rounds.
    int goff[3], sidx[3];
#pragma unroll
    for (int k = 0; k < 3; k++) {
        int i = tid + k * NTHR;
        if (i < NSLOT) {
            int sy = i / FW4;
            int sxx = i - sy * FW4;
            int yy = y0 - R + sy;
            int xx = x0 - R + 4 * sxx;       // 4-aligned; quad fully in or out
            sidx[k] = sy * TILE_W + 4 * sxx;
            goff[k] = (xx >= 0 && xx + 3 < NN && yy >= 0 && yy < NN)
                          ? (yy * NN + xx) : -1;
        } else {
            sidx[k] = -1;
            goff[k] = -1;
        }
    }

    // Register queue: q[k] = cur plane (z0 - 4 + k), this thread's 4 points
    float4 q[9];
#pragma unroll
    for (int k = 0; k < 8; k++) {
        int gz = z0 - R + k;
        q[k] = (gz >= 0) ? ldg4(&cur[gz * PLANE + col])
                         : make_float4(0.f, 0.f, 0.f, 0.f);
    }

    // Prime spA with plane z0
    {
        const float* plane = cur + z0 * PLANE;
        float* fb = &spA[0][0];
#pragma unroll
        for (int k = 0; k < 3; k++) {
            if (sidx[k] >= 0) {
                float4 v = (goff[k] >= 0) ? ldg4(&plane[goff[k]])
                                          : make_float4(0.f, 0.f, 0.f, 0.f);
                *reinterpret_cast<float4*>(fb + sidx[k]) = v;
            }
        }
    }
    __syncthreads();

    StepCtx<FINAL> c{cur, prev, vp, src, out, ref};
    const bool hasprev = (prev != nullptr);
    const int sx = R + 4 * tx;
    const int syc = ty + R;

    double acc_s = 0.0;
    float acc_m = 0.0f;

#pragma unroll 1
    for (int iz = 0; iz < ZC; iz += 2) {
        plane_body<FINAL>(c, spA, spB, z0 + iz, true, hasprev,
                          goff, sidx, col, q, sx, syc, acc_s, acc_m);
        plane_body<FINAL>(c, spB, spA, z0 + iz + 1, (iz + 2 < ZC), hasprev,
                          goff, sidx, col, q, sx, syc, acc_s, acc_m);
    }

    if (FINAL) {
#pragma unroll
        for (int o = 16; o > 0; o >>= 1) {
            acc_s += __shfl_down_sync(0xFFFFFFFFu, acc_s, o);
            acc_m = fmaxf(acc_m, __shfl_down_sync(0xFFFFFFFFu, acc_m, o));
        }
        __shared__ double ss[4];
        __shared__ float sm[4];
        int lane = tid & 31;
        int w = tid >> 5;
        if (lane == 0) { ss[w] = acc_s; sm[w] = acc_m; }
        __syncthreads();
        if (w == 0) {
            acc_s = (lane < 4) ? ss[lane] : 0.0;
            acc_m = (lane < 4) ? sm[lane] : 0.0f;
#pragma unroll
            for (int o = 2; o > 0; o >>= 1) {
                acc_s += __shfl_down_sync(0xFFFFFFFFu, acc_s, o);
                acc_m = fmaxf(acc_m, __shfl_down_sync(0xFFFFFFFFu, acc_m, o));
            }
            if (lane == 0) {
                atomicAdd(&g_sum, acc_s);
                atomicMax(&g_maxbits, __float_as_uint(acc_m));
            }
        }
    }
}

__global__ void finalize_kernel(float* d_out, int n) {
    d_out[0] = (float)(g_sum / (double)n);
    d_out[n + 1] = __uint_as_float(g_maxbits);
}

extern "C" void kernel_launch(void* const* d_in, const int* in_sizes, int n_in,
                              void* d_out, int out_size) {
    const float* vp  = (const float*)d_in[0];
    const float* src = (const float*)d_in[1];
    const float* ref = (const float*)d_in[2];

    static float* bufA = nullptr;
    static float* bufB = nullptr;
    if (!bufA) {
        cudaGetSymbolAddress((void**)&bufA, g_bufA);
        cudaGetSymbolAddress((void**)&bufB, g_bufB);
    }

    const bool has_scalars = (out_size >= VOL + 2);
    float* outp = has_scalars ? ((float*)d_out + 1) : (float*)d_out;

    dim3 blk(TXT, TY);
    dim3 grid(NN / SPANX, NN / TY, NN / ZC);   // (3, 24, 12) = 864 blocks

    init_accum_kernel<<<1, 1>>>();

    const float* s0 = src;

    step_kernel<false><<<grid, blk>>>(s0,   nullptr, vp, src + (size_t)1 * VOL, bufA, nullptr);
    step_kernel<false><<<grid, blk>>>(bufA, s0,      vp, src + (size_t)2 * VOL, bufB, nullptr);
    step_kernel<false><<<grid, blk>>>(bufB, bufA,    vp, src + (size_t)3 * VOL, bufA, nullptr);
    step_kernel<false><<<grid, blk>>>(bufA, bufB,    vp, src + (size_t)4 * VOL, bufB, nullptr);
    step_kernel<false><<<grid, blk>>>(bufB, bufA,    vp, src + (size_t)5 * VOL, bufA, nullptr);
    step_kernel<false><<<grid, blk>>>(bufA, bufB,    vp, src + (size_t)6 * VOL, bufB, nullptr);
    step_kernel<false><<<grid, blk>>>(bufB, bufA,    vp, src + (size_t)7 * VOL, bufA, nullptr);
    step_kernel<false><<<grid, blk>>>(bufA, bufB,    vp, src + (size_t)8 * VOL, bufB, nullptr);
    step_kernel<true><<<grid, blk>>>(bufB, bufA,     vp, src + (size_t)9 * VOL, outp, ref);

    if (has_scalars) {
        finalize_kernel<<<1, 1>>>((float*)d_out, VOL);
    }
}

// round 7
// speedup vs baseline: 3.5505x; 1.0615x over previous
#include <cuda_runtime.h>
#include <cuda_bf16.h>
#include <math.h>
#include <stdint.h>

// ---------------------------------------------------------------------------
// 25-pt (radius-4, 3-axis) wave stencil, 10 scan steps (first trivial),
// then loss = mean((out-ref)^2), max_abs = max|out-ref|.
// R7: cp.async (LDGSTS) smem pipeline, 4-buffer ring, prefetch distance 2;
// z-queue head prefetched one plane ahead; float4 compute (4 x-pts/thread).
// ---------------------------------------------------------------------------

#define NN 192
#define PLANE (NN * NN)
#define VOL (NN * NN * NN)

#define TXT 16
#define TY 8
#define NTHR (TXT * TY)          // 128
#define SPANX (TXT * 4)          // 64 x-points per block
#define ZC 16
#define R  4

#define TILE_H (TY + 2 * R)      // 16
#define TILE_WU (SPANX + 2 * R)  // 72 floats used
#define TILE_W 80                // padded row stride (16B multiple)
#define FW4 (TILE_WU / 4)        // 18 float4 per row
#define NSLOT (TILE_H * FW4)     // 288 fill slots

#define C0 ((float)(-205.0 / 72.0 / 400.0))
#define C1 ((float)(8.0 / 5.0 / 400.0))
#define C2 ((float)(-1.0 / 5.0 / 400.0))
#define C3 ((float)(8.0 / 315.0 / 400.0))
#define C4 ((float)(-1.0 / 560.0 / 400.0))

__device__ float g_bufA[VOL];
__device__ float g_bufB[VOL];
__device__ double g_sum;
__device__ unsigned int g_maxbits;

__global__ void init_accum_kernel() {
    g_sum = 0.0;
    g_maxbits = 0u;
}

__device__ __forceinline__ float4 ldg4(const float* p) {
    return *reinterpret_cast<const float4*>(p);
}
__device__ __forceinline__ float4 ldcs4(const float* p) {
    float4 v;
    asm volatile("ld.global.cs.v4.f32 {%0,%1,%2,%3}, [%4];"
                 : "=f"(v.x), "=f"(v.y), "=f"(v.z), "=f"(v.w) : "l"(p));
    return v;
}
__device__ __forceinline__ float ldcs1(const float* p) {
    float v;
    asm volatile("ld.global.cs.f32 %0, [%1];" : "=f"(v) : "l"(p));
    return v;
}

// Async-fill one plane's tile into the ring buffer at smem addr sbase.
// goff<0 -> zero-fill (src_size=0, pointer clamped in-range).
__device__ __forceinline__ void fill_plane_async(
    uint32_t sbase, const float* gplane, const int* goff, const int* sidx) {
#pragma unroll
    for (int k = 0; k < 3; k++) {
        if (sidx[k] >= 0) {
            const float* srcp = (goff[k] >= 0) ? (gplane + goff[k]) : gplane;
            int sz = (goff[k] >= 0) ? 16 : 0;
            asm volatile("cp.async.cg.shared.global [%0], [%1], 16, %2;"
                         :: "r"(sbase + (uint32_t)sidx[k] * 4u), "l"(srcp), "r"(sz));
        }
    }
    asm volatile("cp.async.commit_group;" ::: "memory");
}

template <bool FINAL>
struct StepCtx {
    const float* cur;
    const float* prev;
    const float* vp;
    const float* src;
    float* out;
    const float* ref;
};

// One z-plane body. consume: smem tile of plane z (ready after wait+barrier).
// fillbase: smem addr of the ring slot for plane z+2 (issued async here).
template <bool FINAL>
__device__ __forceinline__ void plane_body(
    const StepCtx<FINAL>& c,
    const float (&consume)[TILE_H][TILE_W],
    uint32_t fillbase,
    int z, bool hasprev,
    const int* goff, const int* sidx,
    int col,
    float4 q[9],
    int sx, int syc,
    double& acc_s, float& acc_m) {

    const int zoff = z * PLANE;
    const int idx = zoff + col;

    // ---- issue async fill for plane z+2 (clamped), then wait for plane z ----
    {
        int zf = z + 2;
        if (zf > NN - 1) zf = NN - 1;
        fill_plane_async(fillbase, c.cur + zf * PLANE, goff, sidx);
    }
    asm volatile("cp.async.wait_group 2;" ::: "memory");
    __syncthreads();   // plane z's tile visible to all; prior consume complete

    // ---- issue next z-queue head (plane z+5, for NEXT body) + pointwise ----
    float4 qn;
    {
        int zp = z + 5;
        qn = (zp < NN) ? ldg4(&c.cur[zp * PLANE + col])
                       : make_float4(0.f, 0.f, 0.f, 0.f);
    }
    const float4 pv = hasprev ? ldg4(&c.prev[idx]) : make_float4(0.f, 0.f, 0.f, 0.f);
    const float4 vv = ldg4(&c.vp[idx]);
    const float4 sv = ldcs4(&c.src[idx]);

    // ---- x-row taps: xs[j] = consume[syc][sx-4+j], j=0..11 (3 LDS.128) ----
    float xs[12];
#pragma unroll
    for (int j = 0; j < 3; j++) {
        float4 t = *reinterpret_cast<const float4*>(&consume[syc][sx - 4 + 4 * j]);
        xs[4 * j + 0] = t.x;
        xs[4 * j + 1] = t.y;
        xs[4 * j + 2] = t.z;
        xs[4 * j + 3] = t.w;
    }

    float lap[4];
    {
        const float* q4 = &q[4].x;
#pragma unroll
        for (int p = 0; p < 4; p++) lap[p] = (3.0f * C0) * q4[p];
    }
    {
        float4 ym = *reinterpret_cast<const float4*>(&consume[syc - 1][sx]);
        float4 yp = *reinterpret_cast<const float4*>(&consume[syc + 1][sx]);
        const float* q3 = &q[3].x;
        const float* q5 = &q[5].x;
        const float* a = &ym.x;
        const float* b = &yp.x;
#pragma unroll
        for (int p = 0; p < 4; p++)
            lap[p] += C1 * (q3[p] + q5[p] + a[p] + b[p] + xs[p + 3] + xs[p + 5]);
    }
    {
        float4 ym = *reinterpret_cast<const float4*>(&consume[syc - 2][sx]);
        float4 yp = *reinterpret_cast<const float4*>(&consume[syc + 2][sx]);
        const float* q2 = &q[2].x;
        const float* q6 = &q[6].x;
        const float* a = &ym.x;
        const float* b = &yp.x;
#pragma unroll
        for (int p = 0; p < 4; p++)
            lap[p] += C2 * (q2[p] + q6[p] + a[p] + b[p] + xs[p + 2] + xs[p + 6]);
    }
    {
        float4 ym = *reinterpret_cast<const float4*>(&consume[syc - 3][sx]);
        float4 yp = *reinterpret_cast<const float4*>(&consume[syc + 3][sx]);
        const float* q1 = &q[1].x;
        const float* q7 = &q[7].x;
        const float* a = &ym.x;
        const float* b = &yp.x;
#pragma unroll
        for (int p = 0; p < 4; p++)
            lap[p] += C3 * (q1[p] + q7[p] + a[p] + b[p] + xs[p + 1] + xs[p + 7]);
    }
    {
        float4 ym = *reinterpret_cast<const float4*>(&consume[syc - 4][sx]);
        float4 yp = *reinterpret_cast<const float4*>(&consume[syc + 4][sx]);
        const float* q0 = &q[0].x;
        const float* q8 = &q[8].x;
        const float* a = &ym.x;
        const float* b = &yp.x;
#pragma unroll
        for (int p = 0; p < 4; p++)
            lap[p] += C4 * (q0[p] + q8[p] + a[p] + b[p] + xs[p] + xs[p + 8]);
    }

    float4 upd;
    {
        const float* q4 = &q[4].x;
        const float* pvp = &pv.x;
        const float* vvp = &vv.x;
        const float* svp = &sv.x;
        float* u = &upd.x;
#pragma unroll
        for (int p = 0; p < 4; p++)
            u[p] = 2.0f * q4[p] - pvp[p] + vvp[p] * lap[p] + svp[p];
    }

    if (FINAL) {
        const float* u = &upd.x;
#pragma unroll
        for (int p = 0; p < 4; p++) {
            c.out[idx + p] = u[p];
            float e = u[p] - ldcs1(&c.ref[idx + p]);
            acc_s += (double)e * (double)e;
            acc_m = fmaxf(acc_m, fabsf(e));
        }
    } else {
        *reinterpret_cast<float4*>(&c.out[idx]) = upd;
    }

    // shift z-queue; head becomes the prefetched plane z+5
#pragma unroll
    for (int k = 0; k < 8; k++) q[k] = q[k + 1];
    q[8] = qn;
}

template <bool FINAL>
__global__ void __launch_bounds__(NTHR, 6)
step_kernel(const float* __restrict__ cur,
            const float* __restrict__ prev,
            const float* __restrict__ vp,
            const float* __restrict__ src,
            float* __restrict__ out,
            const float* __restrict__ ref) {
    __shared__ float sp[4][TILE_H][TILE_W];   // 4-deep ring

    const int tx = threadIdx.x;
    const int ty = threadIdx.y;
    const int x0 = blockIdx.x * SPANX;
    const int y0 = blockIdx.y * TY;
    const int z0 = blockIdx.z * ZC;
    const int gx = x0 + 4 * tx;
    const int gy = y0 + ty;
    const int tid = ty * TXT + tx;
    const int col = gy * NN + gx;

    // Cooperative fill slots: NSLOT=288 float4 over 128 threads -> 3 rounds.
    int goff[3], sidx[3];
#pragma unroll
    for (int k = 0; k < 3; k++) {
        int i = tid + k * NTHR;
        if (i < NSLOT) {
            int sy = i / FW4;
            int sxx = i - sy * FW4;
            int yy = y0 - R + sy;
            int xx = x0 - R + 4 * sxx;      // quad fully in or fully out
            sidx[k] = sy * TILE_W + 4 * sxx;
            goff[k] = (xx >= 0 && xx + 3 < NN && yy >= 0 && yy < NN)
                          ? (yy * NN + xx) : -1;
        } else {
            sidx[k] = -1;
            goff[k] = -1;
        }
    }

    uint32_t sb[4];
#pragma unroll
    for (int b = 0; b < 4; b++)
        sb[b] = (uint32_t)__cvta_generic_to_shared(&sp[b][0][0]);

    // Prologue: async fills for planes z0 (buf0) and z0+1 (buf1)
    fill_plane_async(sb[0], cur + z0 * PLANE, goff, sidx);
    fill_plane_async(sb[1], cur + (z0 + 1) * PLANE, goff, sidx);

    // z-queue: planes z0-4 .. z0+4
    float4 q[9];
#pragma unroll
    for (int k = 0; k < 9; k++) {
        int gz = z0 - R + k;
        q[k] = (gz >= 0 && gz < NN) ? ldg4(&cur[gz * PLANE + col])
                                    : make_float4(0.f, 0.f, 0.f, 0.f);
    }

    StepCtx<FINAL> c{cur, prev, vp, src, out, ref};
    const bool hasprev = (prev != nullptr);
    const int sx = R + 4 * tx;
    const int syc = ty + R;

    double acc_s = 0.0;
    float acc_m = 0.0f;

    // body j: consume buf j%4, fill buf (j+2)%4 with plane z+2
#pragma unroll 1
    for (int iz = 0; iz < ZC; iz += 4) {
        plane_body<FINAL>(c, sp[0], sb[2], z0 + iz + 0, hasprev,
                          goff, sidx, col, q, sx, syc, acc_s, acc_m);
        plane_body<FINAL>(c, sp[1], sb[3], z0 + iz + 1, hasprev,
                          goff, sidx, col, q, sx, syc, acc_s, acc_m);
        plane_body<FINAL>(c, sp[2], sb[0], z0 + iz + 2, hasprev,
                          goff, sidx, col, q, sx, syc, acc_s, acc_m);
        plane_body<FINAL>(c, sp[3], sb[1], z0 + iz + 3, hasprev,
                          goff, sidx, col, q, sx, syc, acc_s, acc_m);
    }

    if (FINAL) {
#pragma unroll
        for (int o = 16; o > 0; o >>= 1) {
            acc_s += __shfl_down_sync(0xFFFFFFFFu, acc_s, o);
            acc_m = fmaxf(acc_m, __shfl_down_sync(0xFFFFFFFFu, acc_m, o));
        }
        __shared__ double ss[4];
        __shared__ float sm[4];
        int lane = tid & 31;
        int w = tid >> 5;
        if (lane == 0) { ss[w] = acc_s; sm[w] = acc_m; }
        __syncthreads();
        if (w == 0) {
            acc_s = (lane < 4) ? ss[lane] : 0.0;
            acc_m = (lane < 4) ? sm[lane] : 0.0f;
#pragma unroll
            for (int o = 2; o > 0; o >>= 1) {
                acc_s += __shfl_down_sync(0xFFFFFFFFu, acc_s, o);
                acc_m = fmaxf(acc_m, __shfl_down_sync(0xFFFFFFFFu, acc_m, o));
            }
            if (lane == 0) {
                atomicAdd(&g_sum, acc_s);
                atomicMax(&g_maxbits, __float_as_uint(acc_m));
            }
        }
    }
}

__global__ void finalize_kernel(float* d_out, int n) {
    d_out[0] = (float)(g_sum / (double)n);
    d_out[n + 1] = __uint_as_float(g_maxbits);
}

extern "C" void kernel_launch(void* const* d_in, const int* in_sizes, int n_in,
                              void* d_out, int out_size) {
    const float* vp  = (const float*)d_in[0];
    const float* src = (const float*)d_in[1];
    const float* ref = (const float*)d_in[2];

    static float* bufA = nullptr;
    static float* bufB = nullptr;
    if (!bufA) {
        cudaGetSymbolAddress((void**)&bufA, g_bufA);
        cudaGetSymbolAddress((void**)&bufB, g_bufB);
    }

    const bool has_scalars = (out_size >= VOL + 2);
    float* outp = has_scalars ? ((float*)d_out + 1) : (float*)d_out;

    dim3 blk(TXT, TY);
    dim3 grid(NN / SPANX, NN / TY, NN / ZC);   // (3, 24, 12) = 864 blocks

    init_accum_kernel<<<1, 1>>>();

    const float* s0 = src;

    step_kernel<false><<<grid, blk>>>(s0,   nullptr, vp, src + (size_t)1 * VOL, bufA, nullptr);
    step_kernel<false><<<grid, blk>>>(bufA, s0,      vp, src + (size_t)2 * VOL, bufB, nullptr);
    step_kernel<false><<<grid, blk>>>(bufB, bufA,    vp, src + (size_t)3 * VOL, bufA, nullptr);
    step_kernel<false><<<grid, blk>>>(bufA, bufB,    vp, src + (size_t)4 * VOL, bufB, nullptr);
    step_kernel<false><<<grid, blk>>>(bufB, bufA,    vp, src + (size_t)5 * VOL, bufA, nullptr);
    step_kernel<false><<<grid, blk>>>(bufA, bufB,    vp, src + (size_t)6 * VOL, bufB, nullptr);
    step_kernel<false><<<grid, blk>>>(bufB, bufA,    vp, src + (size_t)7 * VOL, bufA, nullptr);
    step_kernel<false><<<grid, blk>>>(bufA, bufB,    vp, src + (size_t)8 * VOL, bufB, nullptr);
    step_kernel<true><<<grid, blk>>>(bufB, bufA,     vp, src + (size_t)9 * VOL, outp, ref);

    if (has_scalars) {
        finalize_kernel<<<1, 1>>>((float*)d_out, VOL);
    }
}